// round 15
// baseline (speedup 1.0000x reference)
#include <cuda_runtime.h>

#define L_DIM 8192
#define B_DIM 4096
#define RANK 8
#define M_SPLITS 128
#define M_CHUNK (L_DIM / M_SPLITS)   // 64
#define B4 (B_DIM / 4)               // 1024 float4 lanes
#define L_TILE 64

typedef unsigned long long u64;

__device__ __forceinline__ void fma2(u64& d, u64 a, u64 b) {
    asm("fma.rn.f32x2 %0, %1, %2, %0;" : "+l"(d) : "l"(a), "l"(b));
}
__device__ __forceinline__ u64 dup2(float v) {
    u64 r;
    asm("mov.b64 %0, {%1, %1};" : "=l"(r) : "f"(v));
    return r;
}
__device__ __forceinline__ u64 pack2(float x, float y) {
    u64 r;
    asm("mov.b64 %0, {%1, %2};" : "=l"(r) : "f"(x), "f"(y));
    return r;
}
__device__ __forceinline__ float2 unpk2(u64 a) {
    float2 f;
    asm("mov.b64 {%0, %1}, %2;" : "=f"(f.x), "=f"(f.y) : "l"(a));
    return f;
}
__device__ __forceinline__ void red_add_v4(float* p, float a, float b,
                                           float c, float d) {
    asm volatile("red.global.add.v4.f32 [%0], {%1, %2, %3, %4};"
                 :: "l"(p), "f"(a), "f"(b), "f"(c), "f"(d) : "memory");
}

// T = V @ inputs -> [RANK, B]. Zero-initialized at load; re-zeroed by out_kernel
// tail each launch, so every kernel_launch call starts from T == 0.
__device__ float g_T[RANK * B_DIM];
// per-b-quadrant completion counters for out_kernel (zero-init, self-resetting)
__device__ int g_count[4];

// stage 1: g_T[r, b] += sum_{m in chunk s} V[r, m] * inputs[m, b]  (RED.v4)
// grid: (B4/256 = 4, M_SPLITS = 128), block: 256, 2 CTAs/SM -> ~3.4 resident
__global__ __launch_bounds__(256, 2) void vx_kernel(
    const float* __restrict__ inp, const float* __restrict__ V) {
    __shared__ u64 Vs[RANK][M_CHUNK];   // duplicated pairs, 4 KB

    const int s = blockIdx.y;
    const int m0 = s * M_CHUNK;
    for (int i = threadIdx.x; i < RANK * M_CHUNK; i += blockDim.x) {
        int r = i >> 6;               // / M_CHUNK
        int mi = i & (M_CHUNK - 1);
        Vs[r][mi] = dup2(V[r * L_DIM + m0 + mi]);
    }
    __syncthreads();

    const int b4 = blockIdx.x * blockDim.x + threadIdx.x;  // 0..1023
    const double2* in2 = (const double2*)inp;   // float4 as 2x u64 halves

    u64 acc[RANK][2];
    #pragma unroll
    for (int r = 0; r < RANK; r++) { acc[r][0] = 0ull; acc[r][1] = 0ull; }

    #pragma unroll 8
    for (int mi = 0; mi < M_CHUNK; mi++) {
        double2 x = __ldcs(&in2[(size_t)(m0 + mi) * B4 + b4]);
        u64 xlo = (u64)__double_as_longlong(x.x);
        u64 xhi = (u64)__double_as_longlong(x.y);
        #pragma unroll
        for (int r = 0; r < RANK; r++) {
            u64 v2 = Vs[r][mi];
            fma2(acc[r][0], v2, xlo);
            fma2(acc[r][1], v2, xhi);
        }
    }

    const int b = b4 * 4;
    #pragma unroll
    for (int r = 0; r < RANK; r++) {
        float2 lo = unpk2(acc[r][0]);
        float2 hi = unpk2(acc[r][1]);
        red_add_v4(&g_T[r * B_DIM + b], lo.x, lo.y, hi.x, hi.y);
    }
}

// stage 2: out[l, b] = sum_r U[r, l] * T[r, b]; tail re-zeroes T for next launch
// Rank-pair form: U compact -> 2 LDS.128 per li; T as rank-pair packs.
// grid: (B4/256 = 4, L_DIM / L_TILE = 128), block: 256, 3 CTAs/SM (74 regs)
__global__ __launch_bounds__(256, 3) void out_kernel(
    const float* __restrict__ U, float* __restrict__ out) {
    __shared__ __align__(16) float Us[L_TILE][RANK];  // compact, 2 KB
    __shared__ int s_last;

    const int t = threadIdx.x;
    const int l0 = blockIdx.y * L_TILE;
    for (int i = t; i < RANK * L_TILE; i += blockDim.x) {
        int r = i >> 6;               // / L_TILE  (coalesced global read)
        int li = i & (L_TILE - 1);
        Us[li][r] = U[r * L_DIM + l0 + li];
    }
    __syncthreads();

    const int b4 = blockIdx.x * blockDim.x + t;  // 0..1023
    const float4* T4 = (const float4*)g_T;

    // tp[rp][c] = packed (T[2rp][col c], T[2rp+1][col c])
    u64 tp[4][4];
    {
        float4 v[RANK];
        #pragma unroll
        for (int r = 0; r < RANK; r++) v[r] = __ldg(&T4[r * B4 + b4]);
        #pragma unroll
        for (int rp = 0; rp < 4; rp++) {
            tp[rp][0] = pack2(v[2 * rp].x, v[2 * rp + 1].x);
            tp[rp][1] = pack2(v[2 * rp].y, v[2 * rp + 1].y);
            tp[rp][2] = pack2(v[2 * rp].z, v[2 * rp + 1].z);
            tp[rp][3] = pack2(v[2 * rp].w, v[2 * rp + 1].w);
        }
    }

    float4* out4 = (float4*)out;
    #pragma unroll 4
    for (int li = 0; li < L_TILE; li++) {
        // 2x LDS.128 broadcast: natural rank pairs (u0,u1)(u2,u3) / (u4,u5)(u6,u7)
        const ulonglong2* up = (const ulonglong2*)&Us[li][0];
        ulonglong2 ua = up[0];
        ulonglong2 ub = up[1];
        float o[4];
        #pragma unroll
        for (int c = 0; c < 4; c++) {
            u64 acc = 0ull;
            fma2(acc, ua.x, tp[0][c]);
            fma2(acc, ua.y, tp[1][c]);
            fma2(acc, ub.x, tp[2][c]);
            fma2(acc, ub.y, tp[3][c]);
            float2 p = unpk2(acc);
            o[c] = __fadd_rn(p.x, p.y);
        }
        __stcs(&out4[(size_t)(l0 + li) * B4 + b4],
               make_float4(o[0], o[1], o[2], o[3]));
    }

    // --- tail: last CTA of this b-quadrant re-zeroes its T slice + counter ---
    __syncthreads();
    __threadfence();
    if (t == 0) {
        int old = atomicAdd(&g_count[blockIdx.x], 1);
        s_last = (old == (int)gridDim.y - 1);
    }
    __syncthreads();
    if (s_last) {
        float4 z = make_float4(0.f, 0.f, 0.f, 0.f);
        float4* Tz = (float4*)g_T;
        #pragma unroll
        for (int r = 0; r < RANK; r++)
            Tz[r * B4 + b4] = z;
        __threadfence();
        if (t == 0) atomicExch(&g_count[blockIdx.x], 0);
    }
}

extern "C" void kernel_launch(void* const* d_in, const int* in_sizes, int n_in,
                              void* d_out, int out_size) {
    const float* inp = (const float*)d_in[0];  // [L, B]
    const float* U   = (const float*)d_in[1];  // [RANK, L]
    const float* V   = (const float*)d_in[2];  // [RANK, L]
    float* out = (float*)d_out;                // [L, B]

    dim3 g1(B4 / 256, M_SPLITS);
    vx_kernel<<<g1, 256>>>(inp, V);

    dim3 g2(B4 / 256, L_DIM / L_TILE);
    out_kernel<<<g2, 256>>>(U, out);
}

// round 16
// speedup vs baseline: 1.0430x; 1.0430x over previous
#include <cuda_runtime.h>

#define L_DIM 8192
#define B_DIM 4096
#define RANK 8
#define M_SPLITS 64
#define M_CHUNK (L_DIM / M_SPLITS)   // 128
#define B4 (B_DIM / 4)               // 1024 float4 lanes
#define L_TILE 64

typedef unsigned long long u64;

__device__ __forceinline__ void fma2(u64& d, u64 a, u64 b) {
    asm("fma.rn.f32x2 %0, %1, %2, %0;" : "+l"(d) : "l"(a), "l"(b));
}
__device__ __forceinline__ u64 dup2(float v) {
    u64 r;
    asm("mov.b64 %0, {%1, %1};" : "=l"(r) : "f"(v));
    return r;
}
__device__ __forceinline__ u64 pack2(float x, float y) {
    u64 r;
    asm("mov.b64 %0, {%1, %2};" : "=l"(r) : "f"(x), "f"(y));
    return r;
}
__device__ __forceinline__ float2 unpk2(u64 a) {
    float2 f;
    asm("mov.b64 {%0, %1}, %2;" : "=f"(f.x), "=f"(f.y) : "l"(a));
    return f;
}
__device__ __forceinline__ void red_add_v4(float* p, float a, float b,
                                           float c, float d) {
    asm volatile("red.global.add.v4.f32 [%0], {%1, %2, %3, %4};"
                 :: "l"(p), "f"(a), "f"(b), "f"(c), "f"(d) : "memory");
}

// T = V @ inputs -> [RANK, B]. Zero-initialized at load; re-zeroed by out_kernel
// tail each launch, so every kernel_launch call starts from T == 0.
__device__ float g_T[RANK * B_DIM];
// per-b-quadrant completion counters for out_kernel (zero-init, self-resetting)
__device__ int g_count[4];

// stage 1: g_T[r, b] += sum_{m in chunk s} V[r, m] * inputs[m, b]  (RED.v4)
// PDL: the load/FMA phase needs nothing from the previous out_kernel; only the
// REDs (which touch g_T after its tail-zeroing) wait on grid dependencies.
// grid: (B4/256 = 4, M_SPLITS = 64), block: 256, 2 CTAs/SM
__global__ __launch_bounds__(256, 2) void vx_kernel(
    const float* __restrict__ inp, const float* __restrict__ V) {
    __shared__ u64 Vs[RANK][M_CHUNK];   // duplicated pairs, 8 KB

    const int s = blockIdx.y;
    const int m0 = s * M_CHUNK;
    for (int i = threadIdx.x; i < RANK * M_CHUNK; i += blockDim.x) {
        int r = i >> 7;               // / M_CHUNK
        int mi = i & (M_CHUNK - 1);
        Vs[r][mi] = dup2(V[r * L_DIM + m0 + mi]);
    }
    __syncthreads();

    const int b4 = blockIdx.x * blockDim.x + threadIdx.x;  // 0..1023
    const double2* in2 = (const double2*)inp;   // float4 as 2x u64 halves

    u64 acc[RANK][2];
    #pragma unroll
    for (int r = 0; r < RANK; r++) { acc[r][0] = 0ull; acc[r][1] = 0ull; }

    #pragma unroll 8
    for (int mi = 0; mi < M_CHUNK; mi++) {
        double2 x = __ldcs(&in2[(size_t)(m0 + mi) * B4 + b4]);
        u64 xlo = (u64)__double_as_longlong(x.x);
        u64 xhi = (u64)__double_as_longlong(x.y);
        #pragma unroll
        for (int r = 0; r < RANK; r++) {
            u64 v2 = Vs[r][mi];
            fma2(acc[r][0], v2, xlo);
            fma2(acc[r][1], v2, xhi);
        }
    }

    // allow the dependent out_kernel to begin launching; wait for the previous
    // grid (prior replay's out_kernel, incl. its T-zeroing) before REDs.
    cudaTriggerProgrammaticLaunchCompletion();
    cudaGridDependencySynchronize();

    const int b = b4 * 4;
    #pragma unroll
    for (int r = 0; r < RANK; r++) {
        float2 lo = unpk2(acc[r][0]);
        float2 hi = unpk2(acc[r][1]);
        red_add_v4(&g_T[r * B_DIM + b], lo.x, lo.y, hi.x, hi.y);
    }
}

// stage 2: out[l, b] = sum_r U[r, l] * T[r, b]; tail re-zeroes T for next launch
// PDL: U staging runs before the grid-dependency wait; T reads after it.
// grid: (B4/256 = 4, L_DIM / L_TILE = 128), block: 256, 3 CTAs/SM (74 regs)
__global__ __launch_bounds__(256, 3) void out_kernel(
    const float* __restrict__ U, float* __restrict__ out) {
    __shared__ __align__(16) float Us[L_TILE][RANK];  // compact, 2 KB
    __shared__ int s_last;

    const int t = threadIdx.x;
    const int l0 = blockIdx.y * L_TILE;
    for (int i = t; i < RANK * L_TILE; i += blockDim.x) {
        int r = i >> 6;               // / L_TILE  (coalesced global read)
        int li = i & (L_TILE - 1);
        Us[li][r] = U[r * L_DIM + l0 + li];
    }
    __syncthreads();

    // wait for vx_kernel (all REDs into g_T flushed) before reading T
    cudaGridDependencySynchronize();

    const int b4 = blockIdx.x * blockDim.x + t;  // 0..1023
    const float4* T4 = (const float4*)g_T;

    // tp[rp][c] = packed (T[2rp][col c], T[2rp+1][col c])
    u64 tp[4][4];
    {
        float4 v[RANK];
        #pragma unroll
        for (int r = 0; r < RANK; r++) v[r] = __ldg(&T4[r * B4 + b4]);
        #pragma unroll
        for (int rp = 0; rp < 4; rp++) {
            tp[rp][0] = pack2(v[2 * rp].x, v[2 * rp + 1].x);
            tp[rp][1] = pack2(v[2 * rp].y, v[2 * rp + 1].y);
            tp[rp][2] = pack2(v[2 * rp].z, v[2 * rp + 1].z);
            tp[rp][3] = pack2(v[2 * rp].w, v[2 * rp + 1].w);
        }
    }

    float4* out4 = (float4*)out;
    #pragma unroll 4
    for (int li = 0; li < L_TILE; li++) {
        // 2x LDS.128 broadcast: natural rank pairs (u0,u1)(u2,u3) / (u4,u5)(u6,u7)
        const ulonglong2* up = (const ulonglong2*)&Us[li][0];
        ulonglong2 ua = up[0];
        ulonglong2 ub = up[1];
        float o[4];
        #pragma unroll
        for (int c = 0; c < 4; c++) {
            u64 acc = 0ull;
            fma2(acc, ua.x, tp[0][c]);
            fma2(acc, ua.y, tp[1][c]);
            fma2(acc, ub.x, tp[2][c]);
            fma2(acc, ub.y, tp[3][c]);
            float2 p = unpk2(acc);
            o[c] = __fadd_rn(p.x, p.y);
        }
        __stcs(&out4[(size_t)(l0 + li) * B4 + b4],
               make_float4(o[0], o[1], o[2], o[3]));
    }

    // let the next replay's vx_kernel begin launching (its REDs still wait on
    // this grid's completion via its own cudaGridDependencySynchronize)
    cudaTriggerProgrammaticLaunchCompletion();

    // --- tail: last CTA of this b-quadrant re-zeroes its T slice + counter ---
    __syncthreads();
    __threadfence();
    if (t == 0) {
        int old = atomicAdd(&g_count[blockIdx.x], 1);
        s_last = (old == (int)gridDim.y - 1);
    }
    __syncthreads();
    if (s_last) {
        float4 z = make_float4(0.f, 0.f, 0.f, 0.f);
        float4* Tz = (float4*)g_T;
        #pragma unroll
        for (int r = 0; r < RANK; r++)
            Tz[r * B4 + b4] = z;
        __threadfence();
        if (t == 0) atomicExch(&g_count[blockIdx.x], 0);
    }
}

extern "C" void kernel_launch(void* const* d_in, const int* in_sizes, int n_in,
                              void* d_out, int out_size) {
    const float* inp = (const float*)d_in[0];  // [L, B]
    const float* U   = (const float*)d_in[1];  // [RANK, L]
    const float* V   = (const float*)d_in[2];  // [RANK, L]
    float* out = (float*)d_out;                // [L, B]

    cudaLaunchAttribute attr[1];
    attr[0].id = cudaLaunchAttributeProgrammaticStreamSerialization;
    attr[0].val.programmaticStreamSerializationAllowed = 1;

    {
        cudaLaunchConfig_t cfg = {};
        cfg.gridDim = dim3(B4 / 256, M_SPLITS);
        cfg.blockDim = dim3(256);
        cfg.stream = 0;
        cfg.attrs = attr;
        cfg.numAttrs = 1;
        cudaLaunchKernelEx(&cfg, vx_kernel, inp, V);
    }
    {
        cudaLaunchConfig_t cfg = {};
        cfg.gridDim = dim3(B4 / 256, L_DIM / L_TILE);
        cfg.blockDim = dim3(256);
        cfg.stream = 0;
        cfg.attrs = attr;
        cfg.numAttrs = 1;
        cudaLaunchKernelEx(&cfg, out_kernel, U, out);
    }
}